// round 17
// baseline (speedup 1.0000x reference)
#include <cuda_runtime.h>
#include <cuda_fp16.h>
#include <cstdint>

// Causal SDPA, fp16 tensor-core flash attention (mma.sync.m16n8k16 + ldmatrix).
// B=4, H=12, S=2048, D=64. Inputs (metadata order): keys, queries, values.
//
// cvt kernel: K,V fp32->fp16 scratch. fa kernel: Q tile 128 rows per CTA
// (2 x m16 blocks per warp -> 2 independent MMA chains for ILP), KV tile 64,
// K/V fragments shared across both m-blocks (each LDSM feeds 4 MMAs).
// cp.async double-buffered; no-max softmax in log2 domain (Q pre-scaled by
// log2e/8); p = ex2.approx.f16x2; row-sums via ones-column MMA at V col 64.

#define SEQ 2048
#define QT 128
#define KT 64
#define STR2 72                   // halves per smem row (144 B)
#define NTOT (4 * 12 * SEQ * 64)
#define TILE_H (KT * STR2)        // 4608 halves
#define TILE_B (TILE_H * 2)       // 9216 bytes
#define QSCALE 0.1803368801111179f   // 0.125 * log2(e)

__device__ __half KH[NTOT];
__device__ __half VH[NTOT];

__device__ __forceinline__ uint32_t pack2(float a, float b) {
    __half2 h = __floats2half2_rn(a, b);
    return *(uint32_t*)&h;
}
__device__ __forceinline__ uint32_t ex2h2(uint32_t x) {
    asm("ex2.approx.f16x2 %0, %0;" : "+r"(x));
    return x;
}

__device__ __forceinline__ void mma_f16(float c[4],
                                        uint32_t a0, uint32_t a1, uint32_t a2, uint32_t a3,
                                        uint32_t b0, uint32_t b1) {
    asm volatile("mma.sync.aligned.m16n8k16.row.col.f32.f16.f16.f32 "
                 "{%0,%1,%2,%3}, {%4,%5,%6,%7}, {%8,%9}, {%0,%1,%2,%3};"
                 : "+f"(c[0]), "+f"(c[1]), "+f"(c[2]), "+f"(c[3])
                 : "r"(a0), "r"(a1), "r"(a2), "r"(a3), "r"(b0), "r"(b1));
}

__device__ __forceinline__ void ldsm4(uint32_t& r0, uint32_t& r1, uint32_t& r2, uint32_t& r3,
                                      uint32_t addr) {
    asm volatile("ldmatrix.sync.aligned.m8n8.x4.shared.b16 {%0,%1,%2,%3}, [%4];"
                 : "=r"(r0), "=r"(r1), "=r"(r2), "=r"(r3) : "r"(addr));
}
__device__ __forceinline__ void ldsm4t(uint32_t& r0, uint32_t& r1, uint32_t& r2, uint32_t& r3,
                                       uint32_t addr) {
    asm volatile("ldmatrix.sync.aligned.m8n8.x4.trans.shared.b16 {%0,%1,%2,%3}, [%4];"
                 : "=r"(r0), "=r"(r1), "=r"(r2), "=r"(r3) : "r"(addr));
}
__device__ __forceinline__ void ldsm2t(uint32_t& r0, uint32_t& r1, uint32_t addr) {
    asm volatile("ldmatrix.sync.aligned.m8n8.x2.trans.shared.b16 {%0,%1}, [%2];"
                 : "=r"(r0), "=r"(r1) : "r"(addr));
}

__device__ __forceinline__ void cp16(uint32_t saddr, const void* gaddr) {
    asm volatile("cp.async.cg.shared.global [%0], [%1], 16;" :: "r"(saddr), "l"(gaddr));
}
__device__ __forceinline__ void cp_commit() {
    asm volatile("cp.async.commit_group;");
}
__device__ __forceinline__ void cp_wait0() {
    asm volatile("cp.async.wait_group 0;");
}

// ---------- kernel 1: K,V fp32 -> fp16 ----------
__global__ __launch_bounds__(256)
void cvt_kernel(const float4* __restrict__ K4, const float4* __restrict__ V4)
{
    int i = blockIdx.x * blockDim.x + threadIdx.x;
    float4 k = K4[i];
    uint2 kh; kh.x = pack2(k.x, k.y); kh.y = pack2(k.z, k.w);
    ((uint2*)KH)[i] = kh;
    float4 v = V4[i];
    uint2 vh; vh.x = pack2(v.x, v.y); vh.y = pack2(v.z, v.w);
    ((uint2*)VH)[i] = vh;
}

// ---------- kernel 2: flash attention ----------
__global__ __launch_bounds__(128, 3)
void fa_f16_kernel(const float* __restrict__ Qg_, float* __restrict__ Og_)
{
    extern __shared__ __half sm2[];
    // layout: [K0 | K1 | V0 | V1]; Q (128 rows) staged across K0|K1 first.
    const uint32_t KbU = (uint32_t)__cvta_generic_to_shared(sm2);

    const int qt   = gridDim.x - 1 - blockIdx.x;   // heavy tiles first
    const int bh   = blockIdx.y;
    const int tid  = threadIdx.x;
    const int w    = tid >> 5;
    const int lane = tid & 31;
    const int lr   = lane >> 2;
    const int lc   = lane & 3;
    const int g    = lane >> 3;
    const int lr8  = lane & 7;

    const size_t base = (size_t)bh * SEQ * 64;
    const float4*  Qg  = (const float4*)(Qg_ + base);
    const __half*  KHp = KH + base;
    const __half*  VHp = VH + base;

    // ldmatrix per-thread offsets (bytes, relative to region base)
    const uint32_t offK = (uint32_t)(((((g >> 1) & 1) * 8 + lr8) * STR2 + (g & 1) * 8) * 2);
    const uint32_t offV = (uint32_t)((((g & 1) * 8 + lr8) * STR2 + (g >> 1) * 8) * 2);
    const uint32_t offL = (uint32_t)((lane & 15) * (STR2 * 2) + 128);

    // cp.async per-thread slice
    const int crow = tid >> 3;
    const int cch  = tid & 7;

    // ---- stage Q (128 rows, fp32->fp16, scaled) across K0|K1; hoist frags ----
    uint32_t qa[2][4][4];
    {
        #pragma unroll
        for (int i = 0; i < 16; i++) {
            int idx = tid + i * 128;              // 0..2047 float4 slots
            int row = idx >> 4, c4 = idx & 15;
            float4 q = Qg[(qt * QT + row) * 16 + c4];
            uint2 h;
            h.x = pack2(q.x * QSCALE, q.y * QSCALE);
            h.y = pack2(q.z * QSCALE, q.w * QSCALE);
            *(uint2*)&sm2[row * STR2 + c4 * 4] = h;   // rows 64.. land in K1: contiguous
        }
        __syncthreads();
        #pragma unroll
        for (int mb = 0; mb < 2; mb++) {
            uint32_t offQ = (uint32_t)(((w * 32 + mb * 16 + (g & 1) * 8 + lr8) * STR2
                                        + (g >> 1) * 8) * 2);
            #pragma unroll
            for (int k = 0; k < 4; k++)
                ldsm4(qa[mb][k][0], qa[mb][k][1], qa[mb][k][2], qa[mb][k][3],
                      KbU + offQ + k * 32);
        }
        // ones column for V stages (cols 64..71)
        {
            int st  = tid >> 6;
            int row = tid & 63;
            uint4 ones = make_uint4(0x00003C00u, 0u, 0u, 0u);
            *(uint4*)&sm2[(2 + st) * TILE_H + row * STR2 + 64] = ones;
        }
        __syncthreads();   // all Q-frag reads done before cp overwrites K0
    }

    // ---- prologue: cp tile 0 -> stage 0 ----
    #pragma unroll
    for (int i = 0; i < 4; i++) {
        int row = crow + i * 16;
        uint32_t so = (uint32_t)(row * (STR2 * 2) + cch * 16);
        cp16(KbU + so,              KHp + (size_t)row * 64 + cch * 8);
        cp16(KbU + so + 2 * TILE_B, VHp + (size_t)row * 64 + cch * 8);
    }
    cp_commit();

    float o[2][8][4];
    float lacc[2][4];
    #pragma unroll
    for (int mb = 0; mb < 2; mb++) {
        #pragma unroll
        for (int n = 0; n < 8; n++)
            #pragma unroll
            for (int j = 0; j < 4; j++) o[mb][n][j] = 0.f;
        lacc[mb][0] = lacc[mb][1] = lacc[mb][2] = lacc[mb][3] = 0.f;
    }

    const int wrow_min = qt * QT + w * 32;
    const int wrow_max = wrow_min + 31;
    const int ktmax    = 2 * qt + 2;

    for (int kt = 0; kt < ktmax; kt++) {
        const int cur = kt & 1;

        cp_wait0();
        __syncthreads();

        if (kt + 1 < ktmax) {
            const int nxt = cur ^ 1;
            #pragma unroll
            for (int i = 0; i < 4; i++) {
                int row = crow + i * 16;
                uint32_t so = (uint32_t)(nxt * TILE_B + row * (STR2 * 2) + cch * 16);
                const size_t goff = (size_t)((kt + 1) * KT + row) * 64 + cch * 8;
                cp16(KbU + so,              KHp + goff);
                cp16(KbU + so + 2 * TILE_B, VHp + goff);
            }
            cp_commit();
        }

        const int kb_g = kt * KT;
        if (kb_g > wrow_max) continue;       // fully masked for this warp

        const uint32_t addrK = KbU + cur * TILE_B + offK;
        const uint32_t vbase = KbU + 2 * TILE_B + cur * TILE_B;
        const uint32_t addrV = vbase + offV;
        const uint32_t addrL = vbase + offL;

        // ---- two 32-key halves ----
        #pragma unroll
        for (int h = 0; h < 2; h++) {
            const int hb_g = kb_g + h * 32;            // first key of half
            if (hb_g > wrow_max) continue;             // fully masked half
            const bool msk = (hb_g + 31 > wrow_min);   // partial mask needed
            const uint32_t hoff = (uint32_t)(h * 32 * (STR2 * 2));

            // ---- QK: S[2][16x32], K frags shared across m-blocks ----
            float s[2][4][4];
            #pragma unroll
            for (int mb = 0; mb < 2; mb++)
                #pragma unroll
                for (int n = 0; n < 4; n++)
                    #pragma unroll
                    for (int j = 0; j < 4; j++) s[mb][n][j] = 0.f;

            #pragma unroll
            for (int k = 0; k < 4; k++) {
                #pragma unroll
                for (int nb2 = 0; nb2 < 2; nb2++) {
                    uint32_t b0, b1, b2, b3;
                    ldsm4(b0, b1, b2, b3,
                          addrK + hoff + nb2 * (16 * STR2 * 2) + k * 32);
                    mma_f16(s[0][2 * nb2],     qa[0][k][0], qa[0][k][1], qa[0][k][2], qa[0][k][3], b0, b1);
                    mma_f16(s[0][2 * nb2 + 1], qa[0][k][0], qa[0][k][1], qa[0][k][2], qa[0][k][3], b2, b3);
                    mma_f16(s[1][2 * nb2],     qa[1][k][0], qa[1][k][1], qa[1][k][2], qa[1][k][3], b0, b1);
                    mma_f16(s[1][2 * nb2 + 1], qa[1][k][0], qa[1][k][1], qa[1][k][2], qa[1][k][3], b2, b3);
                }
            }

            // ---- causal mask ----
            if (msk) {
                #pragma unroll
                for (int mb = 0; mb < 2; mb++) {
                    int qlo = wrow_min + mb * 16 + lr;
                    int qhi = qlo + 8;
                    #pragma unroll
                    for (int n = 0; n < 4; n++) {
                        int key = hb_g + n * 8 + 2 * lc;
                        if (key     > qlo) s[mb][n][0] = -1e30f;
                        if (key + 1 > qlo) s[mb][n][1] = -1e30f;
                        if (key     > qhi) s[mb][n][2] = -1e30f;
                        if (key + 1 > qhi) s[mb][n][3] = -1e30f;
                    }
                }
            }

            // ---- PV + l: p = 2^s (f16x2), V frags shared across m-blocks ----
            #pragma unroll
            for (int j2 = 0; j2 < 2; j2++) {
                uint32_t a0[2], a1[2], a2[2], a3[2];
                #pragma unroll
                for (int mb = 0; mb < 2; mb++) {
                    a0[mb] = ex2h2(pack2(s[mb][2 * j2][0],     s[mb][2 * j2][1]));
                    a1[mb] = ex2h2(pack2(s[mb][2 * j2][2],     s[mb][2 * j2][3]));
                    a2[mb] = ex2h2(pack2(s[mb][2 * j2 + 1][0], s[mb][2 * j2 + 1][1]));
                    a3[mb] = ex2h2(pack2(s[mb][2 * j2 + 1][2], s[mb][2 * j2 + 1][3]));
                }
                const uint32_t joff = hoff + j2 * (16 * STR2 * 2);
                #pragma unroll
                for (int db2 = 0; db2 < 4; db2++) {
                    uint32_t b0, b1, b2, b3;
                    ldsm4t(b0, b1, b2, b3, addrV + joff + db2 * 32);
                    mma_f16(o[0][2 * db2],     a0[0], a1[0], a2[0], a3[0], b0, b1);
                    mma_f16(o[0][2 * db2 + 1], a0[0], a1[0], a2[0], a3[0], b2, b3);
                    mma_f16(o[1][2 * db2],     a0[1], a1[1], a2[1], a3[1], b0, b1);
                    mma_f16(o[1][2 * db2 + 1], a0[1], a1[1], a2[1], a3[1], b2, b3);
                }
                uint32_t lb0, lb1;
                ldsm2t(lb0, lb1, addrL + joff);
                mma_f16(lacc[0], a0[0], a1[0], a2[0], a3[0], lb0, lb1);
                mma_f16(lacc[1], a0[1], a1[1], a2[1], a3[1], lb0, lb1);
            }
        }
    }

    // ---- epilogue ----
    float2* Og = (float2*)(Og_ + base);
    #pragma unroll
    for (int mb = 0; mb < 2; mb++) {
        float l0 = __shfl_sync(0xffffffffu, lacc[mb][0], lane & 0x1C);
        float l1 = __shfl_sync(0xffffffffu, lacc[mb][2], lane & 0x1C);
        float inv0 = 1.0f / l0;
        float inv1 = 1.0f / l1;
        int grow = qt * QT + w * 32 + mb * 16 + lr;
        #pragma unroll
        for (int n = 0; n < 8; n++) {
            Og[ grow      * 32 + n * 4 + lc] = make_float2(o[mb][n][0] * inv0, o[mb][n][1] * inv0);
            Og[(grow + 8) * 32 + n * 4 + lc] = make_float2(o[mb][n][2] * inv1, o[mb][n][3] * inv1);
        }
    }
}

extern "C" void kernel_launch(void* const* d_in, const int* in_sizes, int n_in,
                              void* d_out, int out_size) {
    const float* K = (const float*)d_in[0];
    const float* Q = (const float*)d_in[1];
    const float* V = (const float*)d_in[2];
    float* O = (float*)d_out;

    cvt_kernel<<<NTOT / 4 / 256, 256>>>((const float4*)K, (const float4*)V);

    size_t smem = 4 * TILE_B;     // 36864 B
    cudaFuncSetAttribute(fa_f16_kernel,
                         cudaFuncAttributeMaxDynamicSharedMemorySize, (int)smem);
    dim3 grid(SEQ / QT, 48);
    fa_f16_kernel<<<grid, 128, (int)smem>>>(Q, O);
}